// round 1
// baseline (speedup 1.0000x reference)
#include <cuda_runtime.h>
#include <math.h>

#define B_   64
#define C_   256
#define L_   4096
#define BN_  64
#define E_   4

// ---------------- scratch (device globals; no allocation allowed) ----------
__device__ float d_gatex[B_ * C_];
__device__ int   d_eidx[B_][2];
__device__ float d_gval[B_][2];
__device__ float d_H1[2][B_][BN_][L_];   // 134 MB
__device__ float d_H2[2][B_][BN_][L_];   // 134 MB

// ---------------- G1: gate_x = mean(x, axis=2) -----------------------------
__global__ void gatex_kernel(const float* __restrict__ x) {
    int row = blockIdx.x;                       // b*C_ + c
    const float4* p = (const float4*)(x + (size_t)row * L_);
    float s = 0.f;
    for (int t = threadIdx.x; t < L_ / 4; t += blockDim.x) {
        float4 v = p[t];
        s += v.x + v.y + v.z + v.w;
    }
    __shared__ float sm[256];
    sm[threadIdx.x] = s;
    __syncthreads();
    for (int o = 128; o > 0; o >>= 1) {
        if (threadIdx.x < o) sm[threadIdx.x] += sm[threadIdx.x + o];
        __syncthreads();
    }
    if (threadIdx.x == 0) d_gatex[row] = sm[0] * (1.0f / L_);
}

// ---------------- G2: gating, routing, loss --------------------------------
__device__ __forceinline__ float softplusf(float v) {
    return fmaxf(v, 0.f) + log1pf(expf(-fabsf(v)));
}
__device__ __forceinline__ float normcdff_(float z) {
    return 0.5f * erfcf(-z * 0.70710678118654752440f);
}
__device__ __forceinline__ float cv_squared4(const float* v) {
    float m = 0.25f * (v[0] + v[1] + v[2] + v[3]);
    float var = 0.f;
    #pragma unroll
    for (int i = 0; i < 4; i++) { float d = v[i] - m; var += d * d; }
    var *= (1.0f / 3.0f);                       // ddof = 1
    return var / (m * m + 1e-10f);
}

__global__ void gate_kernel(const float* __restrict__ noise,
                            const float* __restrict__ wg,
                            const float* __restrict__ wn,
                            float* __restrict__ out, long long loss_idx) {
    __shared__ float sh_gates[B_][E_];
    __shared__ float sh_load[B_][E_];
    int b = threadIdx.x;
    if (b < B_) {
        float cl[E_] = {0, 0, 0, 0}, rn[E_] = {0, 0, 0, 0};
        for (int c = 0; c < C_; c++) {
            float gx = d_gatex[b * C_ + c];
            #pragma unroll
            for (int e = 0; e < E_; e++) {
                cl[e] += gx * wg[c * E_ + e];
                rn[e] += gx * wn[c * E_ + e];
            }
        }
        float sd[E_], nz[E_];
        #pragma unroll
        for (int e = 0; e < E_; e++) {
            sd[e] = softplusf(rn[e]) + 0.01f;
            nz[e] = cl[e] + noise[b * E_ + e] * sd[e];
        }
        // softmax (TEMP = 1)
        float mx = fmaxf(fmaxf(nz[0], nz[1]), fmaxf(nz[2], nz[3]));
        float p[E_], s = 0.f;
        #pragma unroll
        for (int e = 0; e < E_; e++) { p[e] = expf(nz[e] - mx); s += p[e]; }
        float lg[E_];
        #pragma unroll
        for (int e = 0; e < E_; e++) lg[e] = p[e] / s;
        // top-3 selection (stable: strict > keeps lowest index on ties)
        int idx[3]; float val[3];
        bool used[E_] = {false, false, false, false};
        for (int r = 0; r < 3; r++) {
            int best = -1; float bv = -1e30f;
            for (int e = 0; e < E_; e++)
                if (!used[e] && lg[e] > bv) { bv = lg[e]; best = e; }
            used[best] = true; idx[r] = best; val[r] = bv;
        }
        // top-2 softmax gates
        float e0 = expf(val[0] - val[0]), e1 = expf(val[1] - val[0]);
        float g0 = e0 / (e0 + e1), g1 = e1 / (e0 + e1);
        #pragma unroll
        for (int e = 0; e < E_; e++) sh_gates[b][e] = 0.f;
        sh_gates[b][idx[0]] = g0;
        sh_gates[b][idx[1]] = g1;
        // load (replicate reference's softmax-space thresholds exactly)
        float thr_in = val[2], thr_out = val[1];
        #pragma unroll
        for (int e = 0; e < E_; e++) {
            bool in_ = nz[e] > thr_in;
            float z = (cl[e] - (in_ ? thr_in : thr_out)) / sd[e];
            sh_load[b][e] = normcdff_(z);
        }
        d_eidx[b][0] = idx[0]; d_eidx[b][1] = idx[1];
        d_gval[b][0] = g0;     d_gval[b][1] = g1;
    }
    __syncthreads();
    if (threadIdx.x == 0) {
        float imp[E_] = {0, 0, 0, 0}, ld[E_] = {0, 0, 0, 0};
        for (int bb = 0; bb < B_; bb++)
            #pragma unroll
            for (int e = 0; e < E_; e++) {
                imp[e] += sh_gates[bb][e];
                ld[e]  += sh_load[bb][e];
            }
        out[loss_idx] = 0.01f * (cv_squared4(imp) + cv_squared4(ld));
    }
}

// ---------------- K1: h1 = relu(W1[e] @ x[b] + b1[e]) ----------------------
// GEMM M=64, K=256, N-tile=64. blockDim=256, 4x4 micro-tiles.
__global__ void k1_kernel(const float* __restrict__ x,
                          const float* __restrict__ W1,
                          const float* __restrict__ b1) {
    int s = blockIdx.z, b = blockIdx.y, ct = blockIdx.x * 64;
    int e = d_eidx[b][s];
    const float* A = W1 + (size_t)e * BN_ * C_;           // 64 x 256
    const float* X = x + (size_t)b * C_ * L_;
    float* O = &d_H1[s][b][0][0];

    __shared__ float As[64][16];
    __shared__ float Xs[16][64];
    int tid = threadIdx.x;
    int tx = tid & 15, ty = tid >> 4;
    float acc[4][4] = {};

    for (int kk = 0; kk < C_; kk += 16) {
        {   // A chunk 64x16, one float4/thread
            int r = tid >> 2, kq = (tid & 3) * 4;
            float4 v = *(const float4*)(A + r * C_ + kk + kq);
            As[r][kq] = v.x; As[r][kq + 1] = v.y; As[r][kq + 2] = v.z; As[r][kq + 3] = v.w;
        }
        {   // X chunk 16x64
            int r = tid >> 4, cq = (tid & 15) * 4;
            *(float4*)&Xs[r][cq] = *(const float4*)(X + (size_t)(kk + r) * L_ + ct + cq);
        }
        __syncthreads();
        #pragma unroll
        for (int k = 0; k < 16; k++) {
            float a0 = As[ty * 4 + 0][k], a1 = As[ty * 4 + 1][k];
            float a2 = As[ty * 4 + 2][k], a3 = As[ty * 4 + 3][k];
            float4 xv = *(float4*)&Xs[k][tx * 4];
            acc[0][0] += a0 * xv.x; acc[0][1] += a0 * xv.y; acc[0][2] += a0 * xv.z; acc[0][3] += a0 * xv.w;
            acc[1][0] += a1 * xv.x; acc[1][1] += a1 * xv.y; acc[1][2] += a1 * xv.z; acc[1][3] += a1 * xv.w;
            acc[2][0] += a2 * xv.x; acc[2][1] += a2 * xv.y; acc[2][2] += a2 * xv.z; acc[2][3] += a2 * xv.w;
            acc[3][0] += a3 * xv.x; acc[3][1] += a3 * xv.y; acc[3][2] += a3 * xv.z; acc[3][3] += a3 * xv.w;
        }
        __syncthreads();
    }
    #pragma unroll
    for (int i = 0; i < 4; i++) {
        int row = ty * 4 + i;
        float bias = b1[e * BN_ + row];
        float4 o;
        o.x = fmaxf(acc[i][0] + bias, 0.f);
        o.y = fmaxf(acc[i][1] + bias, 0.f);
        o.z = fmaxf(acc[i][2] + bias, 0.f);
        o.w = fmaxf(acc[i][3] + bias, 0.f);
        *(float4*)(O + (size_t)row * L_ + ct + tx * 4) = o;
    }
}

// ---------------- K2: h2 = relu(conv3(W2[e], h1) + b2[e]) -------------------
// Conv3 recast as GEMM with K = 64*3 = 192 (W2[e] is contiguous 64x192).
__global__ void k2_kernel(const float* __restrict__ W2,
                          const float* __restrict__ b2) {
    int s = blockIdx.z, b = blockIdx.y, ct = blockIdx.x * 64;
    int e = d_eidx[b][s];
    const float* A = W2 + (size_t)e * BN_ * BN_ * 3;      // 64 x 192
    const float* H = &d_H1[s][b][0][0];
    float* O = &d_H2[s][b][0][0];

    __shared__ float As[64][16];
    __shared__ float Bs[16][64];
    int tid = threadIdx.x;
    int tx = tid & 15, ty = tid >> 4;
    float acc[4][4] = {};

    for (int kk = 0; kk < 192; kk += 16) {
        {   // A chunk
            int r = tid >> 2, kq = (tid & 3) * 4;
            float4 v = *(const float4*)(A + r * 192 + kk + kq);
            As[r][kq] = v.x; As[r][kq + 1] = v.y; As[r][kq + 2] = v.z; As[r][kq + 3] = v.w;
        }
        {   // B chunk: row q -> (ci = q/3, k = q%3), shifted h1 with zero pad
            int r = tid >> 4, tq = (tid & 15) * 4;
            int q = kk + r;
            int ci = q / 3, k = q % 3;
            #pragma unroll
            for (int j = 0; j < 4; j++) {
                int gt = ct + tq + j + k - 1;
                Bs[r][tq + j] = (gt >= 0 && gt < L_) ? H[(size_t)ci * L_ + gt] : 0.f;
            }
        }
        __syncthreads();
        #pragma unroll
        for (int k = 0; k < 16; k++) {
            float a0 = As[ty * 4 + 0][k], a1 = As[ty * 4 + 1][k];
            float a2 = As[ty * 4 + 2][k], a3 = As[ty * 4 + 3][k];
            float4 xv = *(float4*)&Bs[k][tx * 4];
            acc[0][0] += a0 * xv.x; acc[0][1] += a0 * xv.y; acc[0][2] += a0 * xv.z; acc[0][3] += a0 * xv.w;
            acc[1][0] += a1 * xv.x; acc[1][1] += a1 * xv.y; acc[1][2] += a1 * xv.z; acc[1][3] += a1 * xv.w;
            acc[2][0] += a2 * xv.x; acc[2][1] += a2 * xv.y; acc[2][2] += a2 * xv.z; acc[2][3] += a2 * xv.w;
            acc[3][0] += a3 * xv.x; acc[3][1] += a3 * xv.y; acc[3][2] += a3 * xv.z; acc[3][3] += a3 * xv.w;
        }
        __syncthreads();
    }
    #pragma unroll
    for (int i = 0; i < 4; i++) {
        int row = ty * 4 + i;
        float bias = b2[e * BN_ + row];
        float4 o;
        o.x = fmaxf(acc[i][0] + bias, 0.f);
        o.y = fmaxf(acc[i][1] + bias, 0.f);
        o.z = fmaxf(acc[i][2] + bias, 0.f);
        o.w = fmaxf(acc[i][3] + bias, 0.f);
        *(float4*)(O + (size_t)row * L_ + ct + tx * 4) = o;
    }
}

// ---------------- K3: y = sum_s g_s * relu(W3@h2_s + b3 + Wp@x + bp) --------
__global__ void k3_kernel(const float* __restrict__ x,
                          const float* __restrict__ W3,
                          const float* __restrict__ b3,
                          const float* __restrict__ Wp,
                          const float* __restrict__ bp,
                          float* __restrict__ out) {
    int b = blockIdx.z, r0 = blockIdx.y * 64, ct = blockIdx.x * 64;
    int tid = threadIdx.x;
    int tx = tid & 15, ty = tid >> 4;

    __shared__ float As[64][16];
    __shared__ float Bs[16][64];

    float res[4][4] = {};
    const float* Xb = x + (size_t)b * C_ * L_;

    for (int s = 0; s < 2; s++) {
        int e = d_eidx[b][s];
        float g = d_gval[b][s];
        float acc[4][4] = {};

        // part 1: W3[e] (256x64) @ h2_s[b] (64 x Ltile)
        {
            const float* A = W3 + (size_t)e * C_ * BN_;
            const float* Bm = &d_H2[s][b][0][0];
            for (int kk = 0; kk < BN_; kk += 16) {
                {
                    int r = tid >> 2, kq = (tid & 3) * 4;
                    float4 v = *(const float4*)(A + (size_t)(r0 + r) * BN_ + kk + kq);
                    As[r][kq] = v.x; As[r][kq + 1] = v.y; As[r][kq + 2] = v.z; As[r][kq + 3] = v.w;
                }
                {
                    int r = tid >> 4, cq = (tid & 15) * 4;
                    *(float4*)&Bs[r][cq] = *(const float4*)(Bm + (size_t)(kk + r) * L_ + ct + cq);
                }
                __syncthreads();
                #pragma unroll
                for (int k = 0; k < 16; k++) {
                    float a0 = As[ty * 4 + 0][k], a1 = As[ty * 4 + 1][k];
                    float a2 = As[ty * 4 + 2][k], a3 = As[ty * 4 + 3][k];
                    float4 xv = *(float4*)&Bs[k][tx * 4];
                    acc[0][0] += a0 * xv.x; acc[0][1] += a0 * xv.y; acc[0][2] += a0 * xv.z; acc[0][3] += a0 * xv.w;
                    acc[1][0] += a1 * xv.x; acc[1][1] += a1 * xv.y; acc[1][2] += a1 * xv.z; acc[1][3] += a1 * xv.w;
                    acc[2][0] += a2 * xv.x; acc[2][1] += a2 * xv.y; acc[2][2] += a2 * xv.z; acc[2][3] += a2 * xv.w;
                    acc[3][0] += a3 * xv.x; acc[3][1] += a3 * xv.y; acc[3][2] += a3 * xv.z; acc[3][3] += a3 * xv.w;
                }
                __syncthreads();
            }
        }
        // part 2: Wp[e] (256x256) @ x[b]
        {
            const float* A = Wp + (size_t)e * C_ * C_;
            for (int kk = 0; kk < C_; kk += 16) {
                {
                    int r = tid >> 2, kq = (tid & 3) * 4;
                    float4 v = *(const float4*)(A + (size_t)(r0 + r) * C_ + kk + kq);
                    As[r][kq] = v.x; As[r][kq + 1] = v.y; As[r][kq + 2] = v.z; As[r][kq + 3] = v.w;
                }
                {
                    int r = tid >> 4, cq = (tid & 15) * 4;
                    *(float4*)&Bs[r][cq] = *(const float4*)(Xb + (size_t)(kk + r) * L_ + ct + cq);
                }
                __syncthreads();
                #pragma unroll
                for (int k = 0; k < 16; k++) {
                    float a0 = As[ty * 4 + 0][k], a1 = As[ty * 4 + 1][k];
                    float a2 = As[ty * 4 + 2][k], a3 = As[ty * 4 + 3][k];
                    float4 xv = *(float4*)&Bs[k][tx * 4];
                    acc[0][0] += a0 * xv.x; acc[0][1] += a0 * xv.y; acc[0][2] += a0 * xv.z; acc[0][3] += a0 * xv.w;
                    acc[1][0] += a1 * xv.x; acc[1][1] += a1 * xv.y; acc[1][2] += a1 * xv.z; acc[1][3] += a1 * xv.w;
                    acc[2][0] += a2 * xv.x; acc[2][1] += a2 * xv.y; acc[2][2] += a2 * xv.z; acc[2][3] += a2 * xv.w;
                    acc[3][0] += a3 * xv.x; acc[3][1] += a3 * xv.y; acc[3][2] += a3 * xv.z; acc[3][3] += a3 * xv.w;
                }
                __syncthreads();
            }
        }
        #pragma unroll
        for (int i = 0; i < 4; i++) {
            int row = r0 + ty * 4 + i;
            float bias = b3[e * C_ + row] + bp[e * C_ + row];
            #pragma unroll
            for (int j = 0; j < 4; j++)
                res[i][j] += g * fmaxf(acc[i][j] + bias, 0.f);
        }
    }
    #pragma unroll
    for (int i = 0; i < 4; i++) {
        int row = r0 + ty * 4 + i;
        float4 o = make_float4(res[i][0], res[i][1], res[i][2], res[i][3]);
        *(float4*)(out + ((size_t)b * C_ + row) * L_ + ct + tx * 4) = o;
    }
}

// ---------------- launch ----------------------------------------------------
extern "C" void kernel_launch(void* const* d_in, const int* in_sizes, int n_in,
                              void* d_out, int out_size) {
    const float* x     = (const float*)d_in[0];
    const float* noise = (const float*)d_in[1];
    const float* wg    = (const float*)d_in[2];
    const float* wn    = (const float*)d_in[3];
    const float* W1    = (const float*)d_in[4];
    const float* b1    = (const float*)d_in[5];
    const float* W2    = (const float*)d_in[6];
    const float* b2    = (const float*)d_in[7];
    const float* W3    = (const float*)d_in[8];
    const float* b3    = (const float*)d_in[9];
    const float* Wp    = (const float*)d_in[10];
    const float* bp    = (const float*)d_in[11];
    float* out = (float*)d_out;

    long long N = (long long)B_ * C_ * L_;
    long long lidx = ((long long)out_size > N) ? N : ((long long)out_size - 1);

    gatex_kernel<<<B_ * C_, 256>>>(x);
    gate_kernel<<<1, 64>>>(noise, wg, wn, out, lidx);

    dim3 g12(L_ / 64, B_, 2);
    k1_kernel<<<g12, 256>>>(x, W1, b1);
    k2_kernel<<<g12, 256>>>(W2, b2);

    dim3 g3(L_ / 64, C_ / 64, B_);
    k3_kernel<<<g3, 256>>>(x, W3, b3, Wp, bp, out);
}

// round 3
// speedup vs baseline: 1.0276x; 1.0276x over previous
#include <cuda_runtime.h>
#include <math.h>

#define B_   64
#define C_   256
#define L_   4096
#define BN_  64
#define E_   4

// ---------------- scratch (device globals; no allocation allowed) ----------
__device__ float d_gatex[B_ * C_];
__device__ int   d_eidx[B_][2];
__device__ float d_gval[B_][2];
__device__ float d_H1[2][B_][BN_][L_];   // 134 MB
__device__ float d_H2[2][B_][BN_][L_];   // 134 MB

// ---------------- G1: gate_x = mean(x, axis=2) -----------------------------
__global__ void gatex_kernel(const float* __restrict__ x) {
    int row = blockIdx.x;                       // b*C_ + c
    const float4* p = (const float4*)(x + (size_t)row * L_);
    float s = 0.f;
    for (int t = threadIdx.x; t < L_ / 4; t += blockDim.x) {
        float4 v = p[t];
        s += v.x + v.y + v.z + v.w;
    }
    __shared__ float sm[256];
    sm[threadIdx.x] = s;
    __syncthreads();
    for (int o = 128; o > 0; o >>= 1) {
        if (threadIdx.x < o) sm[threadIdx.x] += sm[threadIdx.x + o];
        __syncthreads();
    }
    if (threadIdx.x == 0) d_gatex[row] = sm[0] * (1.0f / L_);
}

// ---------------- G2: gating, routing, loss --------------------------------
__device__ __forceinline__ float softplusf(float v) {
    return fmaxf(v, 0.f) + log1pf(expf(-fabsf(v)));
}
__device__ __forceinline__ float normcdff_(float z) {
    return 0.5f * erfcf(-z * 0.70710678118654752440f);
}
__device__ __forceinline__ float cv_squared4(const float* v) {
    float m = 0.25f * (v[0] + v[1] + v[2] + v[3]);
    float var = 0.f;
    #pragma unroll
    for (int i = 0; i < 4; i++) { float d = v[i] - m; var += d * d; }
    var *= (1.0f / 3.0f);                       // ddof = 1
    return var / (m * m + 1e-10f);
}

__global__ void gate_kernel(const float* __restrict__ noise,
                            const float* __restrict__ wg,
                            const float* __restrict__ wn,
                            float* __restrict__ out, long long loss_idx) {
    __shared__ float sh_gates[B_][E_];
    __shared__ float sh_load[B_][E_];
    int b = threadIdx.x;
    if (b < B_) {
        float cl[E_] = {0, 0, 0, 0}, rn[E_] = {0, 0, 0, 0};
        for (int c = 0; c < C_; c++) {
            float gx = d_gatex[b * C_ + c];
            #pragma unroll
            for (int e = 0; e < E_; e++) {
                cl[e] += gx * wg[c * E_ + e];
                rn[e] += gx * wn[c * E_ + e];
            }
        }
        float sd[E_], nz[E_];
        #pragma unroll
        for (int e = 0; e < E_; e++) {
            sd[e] = softplusf(rn[e]) + 0.01f;
            nz[e] = cl[e] + noise[b * E_ + e] * sd[e];
        }
        float mx = fmaxf(fmaxf(nz[0], nz[1]), fmaxf(nz[2], nz[3]));
        float p[E_], s = 0.f;
        #pragma unroll
        for (int e = 0; e < E_; e++) { p[e] = expf(nz[e] - mx); s += p[e]; }
        float lg[E_];
        #pragma unroll
        for (int e = 0; e < E_; e++) lg[e] = p[e] / s;
        int idx[3]; float val[3];
        bool used[E_] = {false, false, false, false};
        for (int r = 0; r < 3; r++) {
            int best = -1; float bv = -1e30f;
            for (int e = 0; e < E_; e++)
                if (!used[e] && lg[e] > bv) { bv = lg[e]; best = e; }
            used[best] = true; idx[r] = best; val[r] = bv;
        }
        float e0 = 1.0f, e1 = expf(val[1] - val[0]);
        float g0 = e0 / (e0 + e1), g1 = e1 / (e0 + e1);
        #pragma unroll
        for (int e = 0; e < E_; e++) sh_gates[b][e] = 0.f;
        sh_gates[b][idx[0]] = g0;
        sh_gates[b][idx[1]] = g1;
        float thr_in = val[2], thr_out = val[1];
        #pragma unroll
        for (int e = 0; e < E_; e++) {
            bool in_ = nz[e] > thr_in;
            float z = (cl[e] - (in_ ? thr_in : thr_out)) / sd[e];
            sh_load[b][e] = normcdff_(z);
        }
        d_eidx[b][0] = idx[0]; d_eidx[b][1] = idx[1];
        d_gval[b][0] = g0;     d_gval[b][1] = g1;
    }
    __syncthreads();
    if (threadIdx.x == 0) {
        float imp[E_] = {0, 0, 0, 0}, ld[E_] = {0, 0, 0, 0};
        for (int bb = 0; bb < B_; bb++)
            #pragma unroll
            for (int e = 0; e < E_; e++) {
                imp[e] += sh_gates[bb][e];
                ld[e]  += sh_load[bb][e];
            }
        out[loss_idx] = 0.01f * (cv_squared4(imp) + cv_squared4(ld));
    }
}

// ---------------- 8x8 micro-tile FMA ---------------------------------------
__device__ __forceinline__ void fma8x8(float acc[8][8],
                                       const float* __restrict__ avec,
                                       const float* __restrict__ bvec) {
    #pragma unroll
    for (int i = 0; i < 8; i++)
        #pragma unroll
        for (int j = 0; j < 8; j++)
            acc[i][j] += avec[i] * bvec[j];
}

// ---------------- K1: h1 = relu(W1[e] @ x[b] + b1[e]) ----------------------
// M=64, K=256, N-tile=128. 128 threads, 8x8 micro-tiles, A transposed in smem.
__global__ void __launch_bounds__(128, 4)
k1_kernel(const float* __restrict__ x,
          const float* __restrict__ W1,
          const float* __restrict__ b1) {
    int s = blockIdx.z, b = blockIdx.y, ct = blockIdx.x * 128;
    int e = d_eidx[b][s];
    const float* A = W1 + (size_t)e * BN_ * C_;           // 64 x 256 row-major
    const float* X = x + (size_t)b * C_ * L_;
    float* O = &d_H1[s][b][0][0];

    __shared__ float As[16][64];    // transposed: As[k][m]
    __shared__ float Bs[16][128];
    int tid = threadIdx.x;
    int tx = tid & 15, ty = tid >> 4;      // tx: 16 col-groups, ty: 8 row-groups
    float acc[8][8] = {};

    int ar = tid >> 1, akq = (tid & 1) * 8;
    int br = tid >> 3, bc = (tid & 7) * 16;

    for (int kk = 0; kk < C_; kk += 16) {
        {   // A chunk 64x16 -> transposed store
            const float* ap = A + ar * C_ + kk + akq;
            float4 v0 = *(const float4*)(ap);
            float4 v1 = *(const float4*)(ap + 4);
            As[akq + 0][ar] = v0.x; As[akq + 1][ar] = v0.y;
            As[akq + 2][ar] = v0.z; As[akq + 3][ar] = v0.w;
            As[akq + 4][ar] = v1.x; As[akq + 5][ar] = v1.y;
            As[akq + 6][ar] = v1.z; As[akq + 7][ar] = v1.w;
        }
        {   // B chunk 16x128
            const float* bp = X + (size_t)(kk + br) * L_ + ct + bc;
            #pragma unroll
            for (int q = 0; q < 4; q++)
                *(float4*)&Bs[br][bc + q * 4] = *(const float4*)(bp + q * 4);
        }
        __syncthreads();
        #pragma unroll
        for (int k = 0; k < 16; k++) {
            float av[8], bv[8];
            *(float4*)&av[0] = *(float4*)&As[k][ty * 8];
            *(float4*)&av[4] = *(float4*)&As[k][ty * 8 + 4];
            *(float4*)&bv[0] = *(float4*)&Bs[k][tx * 8];
            *(float4*)&bv[4] = *(float4*)&Bs[k][tx * 8 + 4];
            fma8x8(acc, av, bv);
        }
        __syncthreads();
    }
    #pragma unroll
    for (int i = 0; i < 8; i++) {
        int row = ty * 8 + i;
        float bias = b1[e * BN_ + row];
        float* op = O + (size_t)row * L_ + ct + tx * 8;
        float4 o0, o1;
        o0.x = fmaxf(acc[i][0] + bias, 0.f); o0.y = fmaxf(acc[i][1] + bias, 0.f);
        o0.z = fmaxf(acc[i][2] + bias, 0.f); o0.w = fmaxf(acc[i][3] + bias, 0.f);
        o1.x = fmaxf(acc[i][4] + bias, 0.f); o1.y = fmaxf(acc[i][5] + bias, 0.f);
        o1.z = fmaxf(acc[i][6] + bias, 0.f); o1.w = fmaxf(acc[i][7] + bias, 0.f);
        *(float4*)(op)     = o0;
        *(float4*)(op + 4) = o1;
    }
}

// ---------------- K2: h2 = relu(conv3(W2[e], h1) + b2[e]) -------------------
// Conv3 as GEMM with K = 192. Same tiling as K1.
__global__ void __launch_bounds__(128, 4)
k2_kernel(const float* __restrict__ W2,
          const float* __restrict__ b2) {
    int s = blockIdx.z, b = blockIdx.y, ct = blockIdx.x * 128;
    int e = d_eidx[b][s];
    const float* A = W2 + (size_t)e * BN_ * BN_ * 3;      // 64 x 192 row-major
    const float* H = &d_H1[s][b][0][0];
    float* O = &d_H2[s][b][0][0];

    __shared__ float As[16][64];
    __shared__ float Bs[16][128];
    int tid = threadIdx.x;
    int tx = tid & 15, ty = tid >> 4;
    float acc[8][8] = {};

    int ar = tid >> 1, akq = (tid & 1) * 8;
    int br = tid >> 3, bc = (tid & 7) * 16;

    for (int kk = 0; kk < 192; kk += 16) {
        {   // A chunk -> transposed
            const float* ap = A + ar * 192 + kk + akq;
            float4 v0 = *(const float4*)(ap);
            float4 v1 = *(const float4*)(ap + 4);
            As[akq + 0][ar] = v0.x; As[akq + 1][ar] = v0.y;
            As[akq + 2][ar] = v0.z; As[akq + 3][ar] = v0.w;
            As[akq + 4][ar] = v1.x; As[akq + 5][ar] = v1.y;
            As[akq + 6][ar] = v1.z; As[akq + 7][ar] = v1.w;
        }
        {   // B chunk: row q -> (ci = q/3, kp = q%3), shifted h1 with zero pad
            int q = kk + br;
            int ci = q / 3, kp = q - ci * 3;
            const float* src = H + (size_t)ci * L_;
            int base = ct + bc + kp - 1;
            #pragma unroll
            for (int j = 0; j < 16; j++) {
                int gt = base + j;
                Bs[br][bc + j] = (gt >= 0 && gt < L_) ? __ldg(src + gt) : 0.f;
            }
        }
        __syncthreads();
        #pragma unroll
        for (int k = 0; k < 16; k++) {
            float av[8], bv[8];
            *(float4*)&av[0] = *(float4*)&As[k][ty * 8];
            *(float4*)&av[4] = *(float4*)&As[k][ty * 8 + 4];
            *(float4*)&bv[0] = *(float4*)&Bs[k][tx * 8];
            *(float4*)&bv[4] = *(float4*)&Bs[k][tx * 8 + 4];
            fma8x8(acc, av, bv);
        }
        __syncthreads();
    }
    #pragma unroll
    for (int i = 0; i < 8; i++) {
        int row = ty * 8 + i;
        float bias = b2[e * BN_ + row];
        float* op = O + (size_t)row * L_ + ct + tx * 8;
        float4 o0, o1;
        o0.x = fmaxf(acc[i][0] + bias, 0.f); o0.y = fmaxf(acc[i][1] + bias, 0.f);
        o0.z = fmaxf(acc[i][2] + bias, 0.f); o0.w = fmaxf(acc[i][3] + bias, 0.f);
        o1.x = fmaxf(acc[i][4] + bias, 0.f); o1.y = fmaxf(acc[i][5] + bias, 0.f);
        o1.z = fmaxf(acc[i][6] + bias, 0.f); o1.w = fmaxf(acc[i][7] + bias, 0.f);
        *(float4*)(op)     = o0;
        *(float4*)(op + 4) = o1;
    }
}

// ---------------- K3 (per slot): y (+)= g_s * relu(W3@h2 + b3 + Wp@x + bp) --
// Tile 128x128, 256 threads, 8x8 micro-tiles. Two passes: slot 0 writes,
// slot 1 accumulates into out.
template <bool ACCUM>
__global__ void __launch_bounds__(256, 2)
k3_kernel(const float* __restrict__ x,
          const float* __restrict__ W3,
          const float* __restrict__ b3,
          const float* __restrict__ Wp,
          const float* __restrict__ bp,
          float* __restrict__ out, int slot) {
    int b = blockIdx.z, r0 = blockIdx.y * 128, ct = blockIdx.x * 128;
    int e = d_eidx[b][slot];
    float g = d_gval[b][slot];
    int tid = threadIdx.x;
    int tx = tid & 15, ty = tid >> 4;       // 16 x 16 thread grid

    __shared__ float As[16][128];   // transposed: As[k][m]
    __shared__ float Bs[16][128];

    float acc[8][8] = {};
    const float* Xb = x + (size_t)b * C_ * L_;

    int ar = tid >> 1, akq = (tid & 1) * 8;
    int br = tid >> 4, bc = (tid & 15) * 8;

    // part 1: W3[e] (256x64 row-major) rows [r0, r0+128) @ h2[slot][b]
    {
        const float* A = W3 + (size_t)e * C_ * BN_;
        const float* Bm = &d_H2[slot][b][0][0];
        for (int kk = 0; kk < BN_; kk += 16) {
            {
                const float* ap = A + (size_t)(r0 + ar) * BN_ + kk + akq;
                float4 v0 = *(const float4*)(ap);
                float4 v1 = *(const float4*)(ap + 4);
                As[akq + 0][ar] = v0.x; As[akq + 1][ar] = v0.y;
                As[akq + 2][ar] = v0.z; As[akq + 3][ar] = v0.w;
                As[akq + 4][ar] = v1.x; As[akq + 5][ar] = v1.y;
                As[akq + 6][ar] = v1.z; As[akq + 7][ar] = v1.w;
            }
            {
                const float* bp_ = Bm + (size_t)(kk + br) * L_ + ct + bc;
                *(float4*)&Bs[br][bc]     = *(const float4*)(bp_);
                *(float4*)&Bs[br][bc + 4] = *(const float4*)(bp_ + 4);
            }
            __syncthreads();
            #pragma unroll
            for (int k = 0; k < 16; k++) {
                float av[8], bv[8];
                *(float4*)&av[0] = *(float4*)&As[k][ty * 8];
                *(float4*)&av[4] = *(float4*)&As[k][ty * 8 + 4];
                *(float4*)&bv[0] = *(float4*)&Bs[k][tx * 8];
                *(float4*)&bv[4] = *(float4*)&Bs[k][tx * 8 + 4];
                fma8x8(acc, av, bv);
            }
            __syncthreads();
        }
    }
    // part 2: Wp[e] (256x256) rows [r0, r0+128) @ x[b]
    {
        const float* A = Wp + (size_t)e * C_ * C_;
        for (int kk = 0; kk < C_; kk += 16) {
            {
                const float* ap = A + (size_t)(r0 + ar) * C_ + kk + akq;
                float4 v0 = *(const float4*)(ap);
                float4 v1 = *(const float4*)(ap + 4);
                As[akq + 0][ar] = v0.x; As[akq + 1][ar] = v0.y;
                As[akq + 2][ar] = v0.z; As[akq + 3][ar] = v0.w;
                As[akq + 4][ar] = v1.x; As[akq + 5][ar] = v1.y;
                As[akq + 6][ar] = v1.z; As[akq + 7][ar] = v1.w;
            }
            {
                const float* bp_ = Xb + (size_t)(kk + br) * L_ + ct + bc;
                *(float4*)&Bs[br][bc]     = *(const float4*)(bp_);
                *(float4*)&Bs[br][bc + 4] = *(const float4*)(bp_ + 4);
            }
            __syncthreads();
            #pragma unroll
            for (int k = 0; k < 16; k++) {
                float av[8], bv[8];
                *(float4*)&av[0] = *(float4*)&As[k][ty * 8];
                *(float4*)&av[4] = *(float4*)&As[k][ty * 8 + 4];
                *(float4*)&bv[0] = *(float4*)&Bs[k][tx * 8];
                *(float4*)&bv[4] = *(float4*)&Bs[k][tx * 8 + 4];
                fma8x8(acc, av, bv);
            }
            __syncthreads();
        }
    }
    #pragma unroll
    for (int i = 0; i < 8; i++) {
        int row = r0 + ty * 8 + i;
        float bias = b3[e * C_ + row] + bp[e * C_ + row];
        float* op = out + ((size_t)b * C_ + row) * L_ + ct + tx * 8;
        float4 o0, o1;
        o0.x = g * fmaxf(acc[i][0] + bias, 0.f);
        o0.y = g * fmaxf(acc[i][1] + bias, 0.f);
        o0.z = g * fmaxf(acc[i][2] + bias, 0.f);
        o0.w = g * fmaxf(acc[i][3] + bias, 0.f);
        o1.x = g * fmaxf(acc[i][4] + bias, 0.f);
        o1.y = g * fmaxf(acc[i][5] + bias, 0.f);
        o1.z = g * fmaxf(acc[i][6] + bias, 0.f);
        o1.w = g * fmaxf(acc[i][7] + bias, 0.f);
        if (ACCUM) {
            float4 p0 = *(float4*)(op), p1 = *(float4*)(op + 4);
            o0.x += p0.x; o0.y += p0.y; o0.z += p0.z; o0.w += p0.w;
            o1.x += p1.x; o1.y += p1.y; o1.z += p1.z; o1.w += p1.w;
        }
        *(float4*)(op)     = o0;
        *(float4*)(op + 4) = o1;
    }
}

// ---------------- launch ----------------------------------------------------
extern "C" void kernel_launch(void* const* d_in, const int* in_sizes, int n_in,
                              void* d_out, int out_size) {
    const float* x     = (const float*)d_in[0];
    const float* noise = (const float*)d_in[1];
    const float* wg    = (const float*)d_in[2];
    const float* wn    = (const float*)d_in[3];
    const float* W1    = (const float*)d_in[4];
    const float* b1    = (const float*)d_in[5];
    const float* W2    = (const float*)d_in[6];
    const float* b2    = (const float*)d_in[7];
    const float* W3    = (const float*)d_in[8];
    const float* b3    = (const float*)d_in[9];
    const float* Wp    = (const float*)d_in[10];
    const float* bp    = (const float*)d_in[11];
    float* out = (float*)d_out;

    long long N = (long long)B_ * C_ * L_;
    long long lidx = ((long long)out_size > N) ? N : ((long long)out_size - 1);

    gatex_kernel<<<B_ * C_, 256>>>(x);
    gate_kernel<<<1, 64>>>(noise, wg, wn, out, lidx);

    dim3 g12(L_ / 128, B_, 2);
    k1_kernel<<<g12, 128>>>(x, W1, b1);
    k2_kernel<<<g12, 128>>>(W2, b2);

    dim3 g3(L_ / 128, C_ / 128, B_);
    k3_kernel<false><<<g3, 256>>>(x, W3, b3, Wp, bp, out, 0);
    k3_kernel<true ><<<g3, 256>>>(x, W3, b3, Wp, bp, out, 1);
}

// round 9
// speedup vs baseline: 1.3335x; 1.2977x over previous
#include <cuda_runtime.h>
#include <math.h>

#define B_   64
#define C_   256
#define L_   4096
#define BN_  64
#define E_   4

// ---------------- scratch (device globals; no allocation allowed) ----------
__device__ float d_gatex[B_ * C_];
__device__ int   d_eidx[B_][2];
__device__ float d_gval[B_][2];
__device__ float d_H1[2][B_][BN_][L_];   // 134 MB
__device__ float d_H2[2][B_][BN_][L_];   // 134 MB
// transposed weights: [e][k][m]
__device__ float d_W1t[E_][C_][BN_];
__device__ float d_W2t[E_][192][BN_];
__device__ float d_W3t[E_][BN_][C_];
__device__ float d_Wpt[E_][C_][C_];

// ---------------- cp.async helpers -----------------------------------------
__device__ __forceinline__ void cpa16(void* sdst, const void* gsrc) {
    unsigned sa = (unsigned)__cvta_generic_to_shared(sdst);
    asm volatile("cp.async.cg.shared.global [%0], [%1], 16;" :: "r"(sa), "l"(gsrc));
}
#define CPA_COMMIT() asm volatile("cp.async.commit_group;")
#define CPA_WAIT0()  asm volatile("cp.async.wait_group 0;")

// ---------------- weight transposes ----------------------------------------
__global__ void tr_w1(const float* __restrict__ w) {      // [E][64][256] -> [E][256][64]
    for (int i = blockIdx.x * blockDim.x + threadIdx.x; i < E_ * BN_ * C_;
         i += gridDim.x * blockDim.x) {
        int e = i / (BN_ * C_), r = i % (BN_ * C_);
        int m = r / C_, k = r % C_;
        d_W1t[e][k][m] = w[i];
    }
}
__global__ void tr_w2(const float* __restrict__ w) {      // [E][64][192] -> [E][192][64]
    for (int i = blockIdx.x * blockDim.x + threadIdx.x; i < E_ * BN_ * 192;
         i += gridDim.x * blockDim.x) {
        int e = i / (BN_ * 192), r = i % (BN_ * 192);
        int m = r / 192, k = r % 192;
        d_W2t[e][k][m] = w[i];
    }
}
__global__ void tr_w3(const float* __restrict__ w) {      // [E][256][64] -> [E][64][256]
    for (int i = blockIdx.x * blockDim.x + threadIdx.x; i < E_ * C_ * BN_;
         i += gridDim.x * blockDim.x) {
        int e = i / (C_ * BN_), r = i % (C_ * BN_);
        int m = r / BN_, k = r % BN_;
        d_W3t[e][k][m] = w[i];
    }
}
__global__ void tr_wp(const float* __restrict__ w) {      // [E][256][256] -> [E][256][256]
    for (int i = blockIdx.x * blockDim.x + threadIdx.x; i < E_ * C_ * C_;
         i += gridDim.x * blockDim.x) {
        int e = i / (C_ * C_), r = i % (C_ * C_);
        int m = r / C_, k = r % C_;
        d_Wpt[e][k][m] = w[i];
    }
}

// ---------------- G1: gate_x = mean(x, axis=2) -----------------------------
__global__ void gatex_kernel(const float* __restrict__ x) {
    int row = blockIdx.x;
    const float4* p = (const float4*)(x + (size_t)row * L_);
    float s = 0.f;
    for (int t = threadIdx.x; t < L_ / 4; t += blockDim.x) {
        float4 v = p[t];
        s += v.x + v.y + v.z + v.w;
    }
    __shared__ float sm[256];
    sm[threadIdx.x] = s;
    __syncthreads();
    for (int o = 128; o > 0; o >>= 1) {
        if (threadIdx.x < o) sm[threadIdx.x] += sm[threadIdx.x + o];
        __syncthreads();
    }
    if (threadIdx.x == 0) d_gatex[row] = sm[0] * (1.0f / L_);
}

// ---------------- G2: gating, routing, loss --------------------------------
__device__ __forceinline__ float softplusf(float v) {
    return fmaxf(v, 0.f) + log1pf(expf(-fabsf(v)));
}
__device__ __forceinline__ float normcdff_(float z) {
    return 0.5f * erfcf(-z * 0.70710678118654752440f);
}
__device__ __forceinline__ float cv_squared4(const float* v) {
    float m = 0.25f * (v[0] + v[1] + v[2] + v[3]);
    float var = 0.f;
    #pragma unroll
    for (int i = 0; i < 4; i++) { float d = v[i] - m; var += d * d; }
    var *= (1.0f / 3.0f);
    return var / (m * m + 1e-10f);
}

__global__ void gate_kernel(const float* __restrict__ noise,
                            const float* __restrict__ wg,
                            const float* __restrict__ wn,
                            float* __restrict__ out, long long loss_idx) {
    __shared__ float sh_gates[B_][E_];
    __shared__ float sh_load[B_][E_];
    int b = threadIdx.x;
    if (b < B_) {
        float cl[E_] = {0, 0, 0, 0}, rn[E_] = {0, 0, 0, 0};
        for (int c = 0; c < C_; c++) {
            float gx = d_gatex[b * C_ + c];
            #pragma unroll
            for (int e = 0; e < E_; e++) {
                cl[e] += gx * wg[c * E_ + e];
                rn[e] += gx * wn[c * E_ + e];
            }
        }
        float sd[E_], nz[E_];
        #pragma unroll
        for (int e = 0; e < E_; e++) {
            sd[e] = softplusf(rn[e]) + 0.01f;
            nz[e] = cl[e] + noise[b * E_ + e] * sd[e];
        }
        float mx = fmaxf(fmaxf(nz[0], nz[1]), fmaxf(nz[2], nz[3]));
        float p[E_], s = 0.f;
        #pragma unroll
        for (int e = 0; e < E_; e++) { p[e] = expf(nz[e] - mx); s += p[e]; }
        float lg[E_];
        #pragma unroll
        for (int e = 0; e < E_; e++) lg[e] = p[e] / s;
        int idx[3]; float val[3];
        bool used[E_] = {false, false, false, false};
        for (int r = 0; r < 3; r++) {
            int best = -1; float bv = -1e30f;
            for (int e = 0; e < E_; e++)
                if (!used[e] && lg[e] > bv) { bv = lg[e]; best = e; }
            used[best] = true; idx[r] = best; val[r] = bv;
        }
        float e1 = expf(val[1] - val[0]);
        float g0 = 1.0f / (1.0f + e1), g1 = e1 / (1.0f + e1);
        #pragma unroll
        for (int e = 0; e < E_; e++) sh_gates[b][e] = 0.f;
        sh_gates[b][idx[0]] = g0;
        sh_gates[b][idx[1]] = g1;
        float thr_in = val[2], thr_out = val[1];
        #pragma unroll
        for (int e = 0; e < E_; e++) {
            bool in_ = nz[e] > thr_in;
            float z = (cl[e] - (in_ ? thr_in : thr_out)) / sd[e];
            sh_load[b][e] = normcdff_(z);
        }
        d_eidx[b][0] = idx[0]; d_eidx[b][1] = idx[1];
        d_gval[b][0] = g0;     d_gval[b][1] = g1;
    }
    __syncthreads();
    if (threadIdx.x == 0) {
        float imp[E_] = {0, 0, 0, 0}, ld[E_] = {0, 0, 0, 0};
        for (int bb = 0; bb < B_; bb++)
            #pragma unroll
            for (int e = 0; e < E_; e++) {
                imp[e] += sh_gates[bb][e];
                ld[e]  += sh_load[bb][e];
            }
        out[loss_idx] = 0.01f * (cv_squared4(imp) + cv_squared4(ld));
    }
}

// ---------------- 8x8 micro-tile FMA ---------------------------------------
__device__ __forceinline__ void fma8x8(float acc[8][8],
                                       const float* __restrict__ a,
                                       const float* __restrict__ bvec) {
    #pragma unroll
    for (int i = 0; i < 8; i++)
        #pragma unroll
        for (int j = 0; j < 8; j++)
            acc[i][j] += a[i] * bvec[j];
}

// ---------------- K1: h1 = relu(W1t[e] GEMM) -------------------------------
// M=64, K=256, N-tile=128, 128 thr, 8x8 micro, cp.async double-buffer.
__global__ void __launch_bounds__(128, 4)
k1_kernel(const float* __restrict__ x,
          const float* __restrict__ b1) {
    int s = blockIdx.z, b = blockIdx.y, ct = blockIdx.x * 128;
    int e = d_eidx[b][s];
    const float* At = &d_W1t[e][0][0];       // [256][64]
    const float* X = x + (size_t)b * C_ * L_;
    float* O = &d_H1[s][b][0][0];

    __shared__ float As[2][16][64];
    __shared__ float Bs[2][16][128];
    int tid = threadIdx.x;
    int tx = tid & 15, ty = tid >> 4;
    float acc[8][8] = {};

    auto issue = [&](int t, int buf) {
        #pragma unroll
        for (int j = 0; j < 2; j++) {         // A: 256 f4 / 128 thr
            int f = tid + j * 128;
            int row = f >> 4, c4 = f & 15;
            cpa16(&As[buf][row][c4 * 4], At + (size_t)(t * 16 + row) * BN_ + c4 * 4);
        }
        #pragma unroll
        for (int j = 0; j < 4; j++) {         // B: 512 f4 / 128 thr
            int f = tid + j * 128;
            int row = f >> 5, c4 = f & 31;
            cpa16(&Bs[buf][row][c4 * 4], X + (size_t)(t * 16 + row) * L_ + ct + c4 * 4);
        }
        CPA_COMMIT();
    };

    issue(0, 0);
    CPA_WAIT0();
    __syncthreads();
    int p = 0;
    for (int t = 0; t < 16; t++) {
        if (t + 1 < 16) issue(t + 1, p ^ 1);
        #pragma unroll
        for (int k = 0; k < 16; k++) {
            float av[8], bv[8];
            *(float4*)&av[0] = *(float4*)&As[p][k][ty * 8];
            *(float4*)&av[4] = *(float4*)&As[p][k][ty * 8 + 4];
            *(float4*)&bv[0] = *(float4*)&Bs[p][k][tx * 8];
            *(float4*)&bv[4] = *(float4*)&Bs[p][k][tx * 8 + 4];
            fma8x8(acc, av, bv);
        }
        if (t + 1 < 16) CPA_WAIT0();
        __syncthreads();
        p ^= 1;
    }
    #pragma unroll
    for (int i = 0; i < 8; i++) {
        int row = ty * 8 + i;
        float bias = b1[e * BN_ + row];
        float* op = O + (size_t)row * L_ + ct + tx * 8;
        float4 o0, o1;
        o0.x = fmaxf(acc[i][0] + bias, 0.f); o0.y = fmaxf(acc[i][1] + bias, 0.f);
        o0.z = fmaxf(acc[i][2] + bias, 0.f); o0.w = fmaxf(acc[i][3] + bias, 0.f);
        o1.x = fmaxf(acc[i][4] + bias, 0.f); o1.y = fmaxf(acc[i][5] + bias, 0.f);
        o1.z = fmaxf(acc[i][6] + bias, 0.f); o1.w = fmaxf(acc[i][7] + bias, 0.f);
        *(float4*)(op)     = o0;
        *(float4*)(op + 4) = o1;
    }
}

// ---------------- K2: conv3 via halo tile + register tap shift --------------
// 256 thr, tile M=64 x N=128, micro 4x8. Bs holds h1 with 8-col halo each side.
__global__ void __launch_bounds__(256, 3)
k2_kernel(const float* __restrict__ b2) {
    int s = blockIdx.z, b = blockIdx.y, ct = blockIdx.x * 128;
    int e = d_eidx[b][s];
    const float* At = &d_W2t[e][0][0];       // [192][64], row q = ci*3+kp
    const float* H = &d_H1[s][b][0][0];
    float* O = &d_H2[s][b][0][0];

    __shared__ float As[3][16][64];          // [kp][ci][m]
    __shared__ float Bs[16][148];            // [ci][halo cols], word j = col ct-8+j
    int tid = threadIdx.x;
    int tx = tid & 15, ty = tid >> 4;        // tx: 16 col groups of 8; ty: 16 row groups of 4
    float acc[4][8] = {};
    bool interior = (ct != 0) && (ct != L_ - 128);

    for (int cc = 0; cc < 4; cc++) {         // 4 chunks of 16 input channels
        // A fill: 768 f4, 3 per thread
        #pragma unroll
        for (int j = 0; j < 3; j++) {
            int f = tid + j * 256;
            int q = f >> 4, c4 = f & 15;     // q in [0,48)
            int kp = q % 3, ci = q / 3;
            *(float4*)&As[kp][ci][c4 * 4] =
                *(const float4*)(At + (size_t)(cc * 48 + q) * BN_ + c4 * 4);
        }
        // B fill: 16 rows x 144 cols = 576 f4, 3 per thread (guard f<576)
        #pragma unroll
        for (int j = 0; j < 3; j++) {
            int f = tid + j * 256;
            if (f < 576) {
                int row = f / 36, c4 = f % 36;
                int ch = cc * 16 + row;
                int gcol = ct - 8 + c4 * 4;
                const float* src = H + (size_t)ch * L_;
                if (interior) {
                    *(float4*)&Bs[row][c4 * 4] = *(const float4*)(src + gcol);
                } else {
                    float4 v;
                    v.x = (gcol + 0 >= 0 && gcol + 0 < L_) ? src[gcol + 0] : 0.f;
                    v.y = (gcol + 1 >= 0 && gcol + 1 < L_) ? src[gcol + 1] : 0.f;
                    v.z = (gcol + 2 >= 0 && gcol + 2 < L_) ? src[gcol + 2] : 0.f;
                    v.w = (gcol + 3 >= 0 && gcol + 3 < L_) ? src[gcol + 3] : 0.f;
                    *(float4*)&Bs[row][c4 * 4] = v;
                }
            }
        }
        __syncthreads();
        #pragma unroll
        for (int ci = 0; ci < 16; ci++) {
            float bbuf[16];
            // words tx*8+4 .. tx*8+19 (aligned f4 loads)
            *(float4*)&bbuf[0]  = *(float4*)&Bs[ci][tx * 8 + 4];
            *(float4*)&bbuf[4]  = *(float4*)&Bs[ci][tx * 8 + 8];
            *(float4*)&bbuf[8]  = *(float4*)&Bs[ci][tx * 8 + 12];
            *(float4*)&bbuf[12] = *(float4*)&Bs[ci][tx * 8 + 16];
            #pragma unroll
            for (int kp = 0; kp < 3; kp++) {
                float4 a = *(float4*)&As[kp][ci][ty * 4];
                float av[4] = {a.x, a.y, a.z, a.w};
                #pragma unroll
                for (int i = 0; i < 4; i++)
                    #pragma unroll
                    for (int j2 = 0; j2 < 8; j2++)
                        acc[i][j2] += av[i] * bbuf[j2 + kp + 3];
            }
        }
        __syncthreads();
    }
    #pragma unroll
    for (int i = 0; i < 4; i++) {
        int row = ty * 4 + i;
        float bias = b2[e * BN_ + row];
        float* op = O + (size_t)row * L_ + ct + tx * 8;
        float4 o0, o1;
        o0.x = fmaxf(acc[i][0] + bias, 0.f); o0.y = fmaxf(acc[i][1] + bias, 0.f);
        o0.z = fmaxf(acc[i][2] + bias, 0.f); o0.w = fmaxf(acc[i][3] + bias, 0.f);
        o1.x = fmaxf(acc[i][4] + bias, 0.f); o1.y = fmaxf(acc[i][5] + bias, 0.f);
        o1.z = fmaxf(acc[i][6] + bias, 0.f); o1.w = fmaxf(acc[i][7] + bias, 0.f);
        *(float4*)(op)     = o0;
        *(float4*)(op + 4) = o1;
    }
}

// ---------------- K3 GEMM core: cp.async double-buffered --------------------
using T16x128 = float[16][128];
__device__ __forceinline__ void gemm_db_k3(
    const float* __restrict__ At,   // [K][256] rows, take cols [r0, r0+128)
    const float* __restrict__ Bm,   // [K][L_] rows, take cols [ct, ct+128)
    int nchunks, int r0, int ct, int tid,
    T16x128* As, T16x128* Bs, float acc[8][8]) {
    int tx = tid & 15, ty = tid >> 4;
    auto issue = [&](int t, int buf) {
        #pragma unroll
        for (int j = 0; j < 2; j++) {
            int f = tid + j * 256;
            int row = f >> 5, c4 = f & 31;
            cpa16(&As[buf][row][c4 * 4], At + (size_t)(t * 16 + row) * C_ + r0 + c4 * 4);
            cpa16(&Bs[buf][row][c4 * 4], Bm + (size_t)(t * 16 + row) * L_ + ct + c4 * 4);
        }
        CPA_COMMIT();
    };
    issue(0, 0);
    CPA_WAIT0();
    __syncthreads();
    int p = 0;
    for (int t = 0; t < nchunks; t++) {
        if (t + 1 < nchunks) issue(t + 1, p ^ 1);
        #pragma unroll
        for (int k = 0; k < 16; k++) {
            float av[8], bv[8];
            *(float4*)&av[0] = *(float4*)&As[p][k][ty * 8];
            *(float4*)&av[4] = *(float4*)&As[p][k][ty * 8 + 4];
            *(float4*)&bv[0] = *(float4*)&Bs[p][k][tx * 8];
            *(float4*)&bv[4] = *(float4*)&Bs[p][k][tx * 8 + 4];
            fma8x8(acc, av, bv);
        }
        if (t + 1 < nchunks) CPA_WAIT0();
        __syncthreads();
        p ^= 1;
    }
}

// ---------------- K3 (per slot): y (+)= g * relu(W3@h2 + b3 + Wp@x + bp) ----
template <bool ACCUM>
__global__ void __launch_bounds__(256, 2)
k3_kernel(const float* __restrict__ x,
          const float* __restrict__ b3,
          const float* __restrict__ bp,
          float* __restrict__ out, int slot) {
    int b = blockIdx.z, r0 = blockIdx.y * 128, ct = blockIdx.x * 128;
    int e = d_eidx[b][slot];
    float g = d_gval[b][slot];
    int tid = threadIdx.x;
    int tx = tid & 15, ty = tid >> 4;

    __shared__ float As[2][16][128];
    __shared__ float Bs[2][16][128];
    float acc[8][8] = {};

    gemm_db_k3(&d_W3t[e][0][0], &d_H2[slot][b][0][0], 4,  r0, ct, tid, As, Bs, acc);
    gemm_db_k3(&d_Wpt[e][0][0], x + (size_t)b * C_ * L_, 16, r0, ct, tid, As, Bs, acc);

    #pragma unroll
    for (int i = 0; i < 8; i++) {
        int row = r0 + ty * 8 + i;
        float bias = b3[e * C_ + row] + bp[e * C_ + row];
        float* op = out + ((size_t)b * C_ + row) * L_ + ct + tx * 8;
        float4 o0, o1;
        o0.x = g * fmaxf(acc[i][0] + bias, 0.f);
        o0.y = g * fmaxf(acc[i][1] + bias, 0.f);
        o0.z = g * fmaxf(acc[i][2] + bias, 0.f);
        o0.w = g * fmaxf(acc[i][3] + bias, 0.f);
        o1.x = g * fmaxf(acc[i][4] + bias, 0.f);
        o1.y = g * fmaxf(acc[i][5] + bias, 0.f);
        o1.z = g * fmaxf(acc[i][6] + bias, 0.f);
        o1.w = g * fmaxf(acc[i][7] + bias, 0.f);
        if (ACCUM) {
            float4 p0 = *(float4*)(op), p1 = *(float4*)(op + 4);
            o0.x += p0.x; o0.y += p0.y; o0.z += p0.z; o0.w += p0.w;
            o1.x += p1.x; o1.y += p1.y; o1.z += p1.z; o1.w += p1.w;
        }
        *(float4*)(op)     = o0;
        *(float4*)(op + 4) = o1;
    }
}

// ---------------- launch ----------------------------------------------------
extern "C" void kernel_launch(void* const* d_in, const int* in_sizes, int n_in,
                              void* d_out, int out_size) {
    const float* x     = (const float*)d_in[0];
    const float* noise = (const float*)d_in[1];
    const float* wg    = (const float*)d_in[2];
    const float* wn    = (const float*)d_in[3];
    const float* W1    = (const float*)d_in[4];
    const float* b1    = (const float*)d_in[5];
    const float* W2    = (const float*)d_in[6];
    const float* b2    = (const float*)d_in[7];
    const float* W3    = (const float*)d_in[8];
    const float* b3    = (const float*)d_in[9];
    const float* Wp    = (const float*)d_in[10];
    const float* bp    = (const float*)d_in[11];
    float* out = (float*)d_out;

    long long N = (long long)B_ * C_ * L_;
    long long lidx = ((long long)out_size > N) ? N : ((long long)out_size - 1);

    tr_w1<<<64, 256>>>(W1);
    tr_w2<<<64, 256>>>(W2);
    tr_w3<<<64, 256>>>(W3);
    tr_wp<<<128, 256>>>(Wp);

    gatex_kernel<<<B_ * C_, 256>>>(x);
    gate_kernel<<<1, 64>>>(noise, wg, wn, out, lidx);

    dim3 g12(L_ / 128, B_, 2);
    k1_kernel<<<g12, 128>>>(x, b1);
    k2_kernel<<<g12, 256>>>(b2);

    dim3 g3(L_ / 128, C_ / 128, B_);
    k3_kernel<false><<<g3, 256>>>(x, b3, bp, out, 0);
    k3_kernel<true ><<<g3, 256>>>(x, b3, bp, out, 1);
}

// round 17
// speedup vs baseline: 1.7211x; 1.2907x over previous
#include <cuda_runtime.h>
#include <cuda_bf16.h>
#include <math.h>
#include <stdint.h>

#define B_   64
#define C_   256
#define L_   4096
#define BN_  64
#define E_   4

// ---------------- scratch (device globals; no allocation allowed) ----------
__device__ float d_gatex[B_ * C_];
__device__ int   d_eidx[B_][2];
__device__ float d_gval[B_][2];
__device__ float d_H1[2][B_][BN_][L_];
__device__ float d_H2[2][B_][BN_][L_];
__device__ float d_W1t[E_][C_][BN_];
__device__ float d_W2t[E_][192][BN_];
// bf16 hi/lo split operands for mma.sync K3
__device__ __nv_bfloat16 d_Ah[E_][C_][320];        // A = [W3 | Wp] rows, k-major
__device__ __nv_bfloat16 d_Al[E_][C_][320];
__device__ __nv_bfloat16 d_xth[B_][L_][C_];        // x transposed [l][c]
__device__ __nv_bfloat16 d_xtl[B_][L_][C_];
__device__ __nv_bfloat16 d_h2th[2][B_][L_][BN_];   // H2 transposed [l][c]
__device__ __nv_bfloat16 d_h2tl[2][B_][L_][BN_];

// ---------------- cp.async helpers -----------------------------------------
__device__ __forceinline__ void cpa16(void* sdst, const void* gsrc) {
    unsigned sa = (unsigned)__cvta_generic_to_shared(sdst);
    asm volatile("cp.async.cg.shared.global [%0], [%1], 16;" :: "r"(sa), "l"(gsrc));
}
#define CPA_COMMIT() asm volatile("cp.async.commit_group;")
#define CPA_WAIT0()  asm volatile("cp.async.wait_group 0;")

// ---------------- weight transposes / conversions ---------------------------
__global__ void tr_w1(const float* __restrict__ w) {
    for (int i = blockIdx.x * blockDim.x + threadIdx.x; i < E_ * BN_ * C_;
         i += gridDim.x * blockDim.x) {
        int e = i / (BN_ * C_), r = i % (BN_ * C_);
        d_W1t[e][r % C_][r / C_] = w[i];
    }
}
__global__ void tr_w2(const float* __restrict__ w) {
    for (int i = blockIdx.x * blockDim.x + threadIdx.x; i < E_ * BN_ * 192;
         i += gridDim.x * blockDim.x) {
        int e = i / (BN_ * 192), r = i % (BN_ * 192);
        d_W2t[e][r % 192][r / 192] = w[i];
    }
}
__global__ void conv_w(const float* __restrict__ W3, const float* __restrict__ Wp) {
    for (int i = blockIdx.x * blockDim.x + threadIdx.x; i < E_ * C_ * 320;
         i += gridDim.x * blockDim.x) {
        int e = i / (C_ * 320), r = i % (C_ * 320);
        int m = r / 320, k = r % 320;
        float v = (k < 64) ? W3[((size_t)e * C_ + m) * BN_ + k]
                           : Wp[((size_t)e * C_ + m) * C_ + (k - 64)];
        __nv_bfloat16 hi = __float2bfloat16(v);
        __nv_bfloat16 lo = __float2bfloat16(v - __bfloat162float(hi));
        d_Ah[e][m][k] = hi;
        d_Al[e][m][k] = lo;
    }
}
// transpose+split x: [b][c][l] -> [b][l][c]
__global__ void conv_xt(const float* __restrict__ x) {
    __shared__ float t[32][33];
    int l0 = blockIdx.x * 32, c0 = blockIdx.y * 32, b = blockIdx.z;
    int tx = threadIdx.x, ty = threadIdx.y;
    #pragma unroll
    for (int j = 0; j < 4; j++) {
        int cc = ty + j * 8;
        t[cc][tx] = x[((size_t)b * C_ + c0 + cc) * L_ + l0 + tx];
    }
    __syncthreads();
    #pragma unroll
    for (int j = 0; j < 4; j++) {
        int ll = ty + j * 8;
        float v = t[tx][ll];
        __nv_bfloat16 hi = __float2bfloat16(v);
        __nv_bfloat16 lo = __float2bfloat16(v - __bfloat162float(hi));
        d_xth[b][l0 + ll][c0 + tx] = hi;
        d_xtl[b][l0 + ll][c0 + tx] = lo;
    }
}
// transpose+split H2: [s][b][c=64][l] -> [s][b][l][64]
__global__ void conv_h2t() {
    __shared__ float t[32][33];
    int l0 = blockIdx.x * 32, c0 = blockIdx.y * 32;
    int s = blockIdx.z >> 6, b = blockIdx.z & 63;
    int tx = threadIdx.x, ty = threadIdx.y;
    #pragma unroll
    for (int j = 0; j < 4; j++) {
        int cc = ty + j * 8;
        t[cc][tx] = d_H2[s][b][c0 + cc][l0 + tx];
    }
    __syncthreads();
    #pragma unroll
    for (int j = 0; j < 4; j++) {
        int ll = ty + j * 8;
        float v = t[tx][ll];
        __nv_bfloat16 hi = __float2bfloat16(v);
        __nv_bfloat16 lo = __float2bfloat16(v - __bfloat162float(hi));
        d_h2th[s][b][l0 + ll][c0 + tx] = hi;
        d_h2tl[s][b][l0 + ll][c0 + tx] = lo;
    }
}

// ---------------- G1: gate_x = mean(x, axis=2) -----------------------------
__global__ void gatex_kernel(const float* __restrict__ x) {
    int row = blockIdx.x;
    const float4* p = (const float4*)(x + (size_t)row * L_);
    float s = 0.f;
    for (int t = threadIdx.x; t < L_ / 4; t += blockDim.x) {
        float4 v = p[t];
        s += v.x + v.y + v.z + v.w;
    }
    __shared__ float sm[256];
    sm[threadIdx.x] = s;
    __syncthreads();
    for (int o = 128; o > 0; o >>= 1) {
        if (threadIdx.x < o) sm[threadIdx.x] += sm[threadIdx.x + o];
        __syncthreads();
    }
    if (threadIdx.x == 0) d_gatex[row] = sm[0] * (1.0f / L_);
}

// ---------------- G2: gating, routing, loss --------------------------------
__device__ __forceinline__ float softplusf(float v) {
    return fmaxf(v, 0.f) + log1pf(expf(-fabsf(v)));
}
__device__ __forceinline__ float normcdff_(float z) {
    return 0.5f * erfcf(-z * 0.70710678118654752440f);
}
__device__ __forceinline__ float cv_squared4(const float* v) {
    float m = 0.25f * (v[0] + v[1] + v[2] + v[3]);
    float var = 0.f;
    #pragma unroll
    for (int i = 0; i < 4; i++) { float d = v[i] - m; var += d * d; }
    var *= (1.0f / 3.0f);
    return var / (m * m + 1e-10f);
}

__global__ void gate_kernel(const float* __restrict__ noise,
                            const float* __restrict__ wg,
                            const float* __restrict__ wn,
                            float* __restrict__ out, long long loss_idx) {
    __shared__ float sh_gates[B_][E_];
    __shared__ float sh_load[B_][E_];
    int b = threadIdx.x;
    if (b < B_) {
        float cl[E_] = {0, 0, 0, 0}, rn[E_] = {0, 0, 0, 0};
        for (int c = 0; c < C_; c++) {
            float gx = d_gatex[b * C_ + c];
            #pragma unroll
            for (int e = 0; e < E_; e++) {
                cl[e] += gx * wg[c * E_ + e];
                rn[e] += gx * wn[c * E_ + e];
            }
        }
        float sd[E_], nz[E_];
        #pragma unroll
        for (int e = 0; e < E_; e++) {
            sd[e] = softplusf(rn[e]) + 0.01f;
            nz[e] = cl[e] + noise[b * E_ + e] * sd[e];
        }
        float mx = fmaxf(fmaxf(nz[0], nz[1]), fmaxf(nz[2], nz[3]));
        float p[E_], s = 0.f;
        #pragma unroll
        for (int e = 0; e < E_; e++) { p[e] = expf(nz[e] - mx); s += p[e]; }
        float lg[E_];
        #pragma unroll
        for (int e = 0; e < E_; e++) lg[e] = p[e] / s;
        int idx[3]; float val[3];
        bool used[E_] = {false, false, false, false};
        for (int r = 0; r < 3; r++) {
            int best = -1; float bv = -1e30f;
            for (int e = 0; e < E_; e++)
                if (!used[e] && lg[e] > bv) { bv = lg[e]; best = e; }
            used[best] = true; idx[r] = best; val[r] = bv;
        }
        float e1 = expf(val[1] - val[0]);
        float g0 = 1.0f / (1.0f + e1), g1 = e1 / (1.0f + e1);
        #pragma unroll
        for (int e = 0; e < E_; e++) sh_gates[b][e] = 0.f;
        sh_gates[b][idx[0]] = g0;
        sh_gates[b][idx[1]] = g1;
        float thr_in = val[2], thr_out = val[1];
        #pragma unroll
        for (int e = 0; e < E_; e++) {
            bool in_ = nz[e] > thr_in;
            float z = (cl[e] - (in_ ? thr_in : thr_out)) / sd[e];
            sh_load[b][e] = normcdff_(z);
        }
        d_eidx[b][0] = idx[0]; d_eidx[b][1] = idx[1];
        d_gval[b][0] = g0;     d_gval[b][1] = g1;
    }
    __syncthreads();
    if (threadIdx.x == 0) {
        float imp[E_] = {0, 0, 0, 0}, ld[E_] = {0, 0, 0, 0};
        for (int bb = 0; bb < B_; bb++)
            #pragma unroll
            for (int e = 0; e < E_; e++) {
                imp[e] += sh_gates[bb][e];
                ld[e]  += sh_load[bb][e];
            }
        out[loss_idx] = 0.01f * (cv_squared4(imp) + cv_squared4(ld));
    }
}

// ---------------- 8x8 micro-tile FMA ---------------------------------------
__device__ __forceinline__ void fma8x8(float acc[8][8],
                                       const float* __restrict__ a,
                                       const float* __restrict__ bvec) {
    #pragma unroll
    for (int i = 0; i < 8; i++)
        #pragma unroll
        for (int j = 0; j < 8; j++)
            acc[i][j] += a[i] * bvec[j];
}

// ---------------- K1 (fp32, cp.async double-buffer) -------------------------
__global__ void __launch_bounds__(128, 4)
k1_kernel(const float* __restrict__ x,
          const float* __restrict__ b1) {
    int s = blockIdx.z, b = blockIdx.y, ct = blockIdx.x * 128;
    int e = d_eidx[b][s];
    const float* At = &d_W1t[e][0][0];
    const float* X = x + (size_t)b * C_ * L_;
    float* O = &d_H1[s][b][0][0];

    __shared__ float As[2][16][64];
    __shared__ float Bs[2][16][128];
    int tid = threadIdx.x;
    int tx = tid & 15, ty = tid >> 4;
    float acc[8][8] = {};

    auto issue = [&](int t, int buf) {
        #pragma unroll
        for (int j = 0; j < 2; j++) {
            int f = tid + j * 128;
            int row = f >> 4, c4 = f & 15;
            cpa16(&As[buf][row][c4 * 4], At + (size_t)(t * 16 + row) * BN_ + c4 * 4);
        }
        #pragma unroll
        for (int j = 0; j < 4; j++) {
            int f = tid + j * 128;
            int row = f >> 5, c4 = f & 31;
            cpa16(&Bs[buf][row][c4 * 4], X + (size_t)(t * 16 + row) * L_ + ct + c4 * 4);
        }
        CPA_COMMIT();
    };

    issue(0, 0);
    CPA_WAIT0();
    __syncthreads();
    int p = 0;
    for (int t = 0; t < 16; t++) {
        if (t + 1 < 16) issue(t + 1, p ^ 1);
        #pragma unroll
        for (int k = 0; k < 16; k++) {
            float av[8], bv[8];
            *(float4*)&av[0] = *(float4*)&As[p][k][ty * 8];
            *(float4*)&av[4] = *(float4*)&As[p][k][ty * 8 + 4];
            *(float4*)&bv[0] = *(float4*)&Bs[p][k][tx * 8];
            *(float4*)&bv[4] = *(float4*)&Bs[p][k][tx * 8 + 4];
            fma8x8(acc, av, bv);
        }
        if (t + 1 < 16) CPA_WAIT0();
        __syncthreads();
        p ^= 1;
    }
    #pragma unroll
    for (int i = 0; i < 8; i++) {
        int row = ty * 8 + i;
        float bias = b1[e * BN_ + row];
        float* op = O + (size_t)row * L_ + ct + tx * 8;
        float4 o0, o1;
        o0.x = fmaxf(acc[i][0] + bias, 0.f); o0.y = fmaxf(acc[i][1] + bias, 0.f);
        o0.z = fmaxf(acc[i][2] + bias, 0.f); o0.w = fmaxf(acc[i][3] + bias, 0.f);
        o1.x = fmaxf(acc[i][4] + bias, 0.f); o1.y = fmaxf(acc[i][5] + bias, 0.f);
        o1.z = fmaxf(acc[i][6] + bias, 0.f); o1.w = fmaxf(acc[i][7] + bias, 0.f);
        *(float4*)(op)     = o0;
        *(float4*)(op + 4) = o1;
    }
}

// ---------------- K2 (fp32 halo conv) ---------------------------------------
__global__ void __launch_bounds__(256, 3)
k2_kernel(const float* __restrict__ b2) {
    int s = blockIdx.z, b = blockIdx.y, ct = blockIdx.x * 128;
    int e = d_eidx[b][s];
    const float* At = &d_W2t[e][0][0];
    const float* H = &d_H1[s][b][0][0];
    float* O = &d_H2[s][b][0][0];

    __shared__ float As[3][16][64];
    __shared__ float Bs[16][148];
    int tid = threadIdx.x;
    int tx = tid & 15, ty = tid >> 4;
    float acc[4][8] = {};
    bool interior = (ct != 0) && (ct != L_ - 128);

    for (int cc = 0; cc < 4; cc++) {
        #pragma unroll
        for (int j = 0; j < 3; j++) {
            int f = tid + j * 256;
            int q = f >> 4, c4 = f & 15;
            int kp = q % 3, ci = q / 3;
            *(float4*)&As[kp][ci][c4 * 4] =
                *(const float4*)(At + (size_t)(cc * 48 + q) * BN_ + c4 * 4);
        }
        #pragma unroll
        for (int j = 0; j < 3; j++) {
            int f = tid + j * 256;
            if (f < 576) {
                int row = f / 36, c4 = f % 36;
                int ch = cc * 16 + row;
                int gcol = ct - 8 + c4 * 4;
                const float* src = H + (size_t)ch * L_;
                if (interior) {
                    *(float4*)&Bs[row][c4 * 4] = *(const float4*)(src + gcol);
                } else {
                    float4 v;
                    v.x = (gcol + 0 >= 0 && gcol + 0 < L_) ? src[gcol + 0] : 0.f;
                    v.y = (gcol + 1 >= 0 && gcol + 1 < L_) ? src[gcol + 1] : 0.f;
                    v.z = (gcol + 2 >= 0 && gcol + 2 < L_) ? src[gcol + 2] : 0.f;
                    v.w = (gcol + 3 >= 0 && gcol + 3 < L_) ? src[gcol + 3] : 0.f;
                    *(float4*)&Bs[row][c4 * 4] = v;
                }
            }
        }
        __syncthreads();
        #pragma unroll
        for (int ci = 0; ci < 16; ci++) {
            float bbuf[16];
            *(float4*)&bbuf[0]  = *(float4*)&Bs[ci][tx * 8 + 4];
            *(float4*)&bbuf[4]  = *(float4*)&Bs[ci][tx * 8 + 8];
            *(float4*)&bbuf[8]  = *(float4*)&Bs[ci][tx * 8 + 12];
            *(float4*)&bbuf[12] = *(float4*)&Bs[ci][tx * 8 + 16];
            #pragma unroll
            for (int kp = 0; kp < 3; kp++) {
                float4 a = *(float4*)&As[kp][ci][ty * 4];
                float av[4] = {a.x, a.y, a.z, a.w};
                #pragma unroll
                for (int i = 0; i < 4; i++)
                    #pragma unroll
                    for (int j2 = 0; j2 < 8; j2++)
                        acc[i][j2] += av[i] * bbuf[j2 + kp + 3];
            }
        }
        __syncthreads();
    }
    #pragma unroll
    for (int i = 0; i < 4; i++) {
        int row = ty * 4 + i;
        float bias = b2[e * BN_ + row];
        float* op = O + (size_t)row * L_ + ct + tx * 8;
        float4 o0, o1;
        o0.x = fmaxf(acc[i][0] + bias, 0.f); o0.y = fmaxf(acc[i][1] + bias, 0.f);
        o0.z = fmaxf(acc[i][2] + bias, 0.f); o0.w = fmaxf(acc[i][3] + bias, 0.f);
        o1.x = fmaxf(acc[i][4] + bias, 0.f); o1.y = fmaxf(acc[i][5] + bias, 0.f);
        o1.z = fmaxf(acc[i][6] + bias, 0.f); o1.w = fmaxf(acc[i][7] + bias, 0.f);
        *(float4*)(op)     = o0;
        *(float4*)(op + 4) = o1;
    }
}

// ---------------- K3: mma.sync bf16 hi/lo split GEMM -------------------------
// Block 256 thr (8 warps), tile M=128 x N=64, warp tile 32x32, K=320 in 10
// chunks of 32. 3 passes (AhBh, AhBl, AlBh), both slots in-register, fused
// bias+relu+gate epilogue. A/B smem rows padded to 40 bf16 (conflict-free
// fragment loads: bank = (row*20 + tig) % 32 covers all 32).
#define K3_AS_STRIDE 40
#define K3_AS_ELEMS  (4 * 128 * K3_AS_STRIDE)
#define K3_BS_ELEMS  (4 * 64 * K3_AS_STRIDE)
#define K3_SMEM      ((K3_AS_ELEMS + K3_BS_ELEMS) * 2)

__device__ __forceinline__ void mma16816(float d[4], uint32_t a0, uint32_t a1,
                                         uint32_t a2, uint32_t a3,
                                         uint32_t b0, uint32_t b1) {
    asm volatile(
        "mma.sync.aligned.m16n8k16.row.col.f32.bf16.bf16.f32 "
        "{%0,%1,%2,%3}, {%4,%5,%6,%7}, {%8,%9}, {%0,%1,%2,%3};"
        : "+f"(d[0]), "+f"(d[1]), "+f"(d[2]), "+f"(d[3])
        : "r"(a0), "r"(a1), "r"(a2), "r"(a3), "r"(b0), "r"(b1));
}

__global__ void __launch_bounds__(256, 2)
k3mma_kernel(const float* __restrict__ b3,
             const float* __restrict__ bp,
             float* __restrict__ out) {
    extern __shared__ __nv_bfloat16 smem[];
    __nv_bfloat16* As = smem;                 // [4][128][40]
    __nv_bfloat16* Bs = smem + K3_AS_ELEMS;   // [4][64][40]

    int tid = threadIdx.x;
    int b = blockIdx.z, r0 = blockIdx.y * 128, ct = blockIdx.x * 64;
    int e0 = d_eidx[b][0], e1 = d_eidx[b][1];
    float g0 = d_gval[b][0], g1 = d_gval[b][1];

    int w = tid >> 5, lane = tid & 31;
    int wm = w & 3, wn = w >> 2;              // warp tile: rows wm*32, cols wn*32
    int g = lane >> 2, tig = lane & 3;

    float acc[2][2][4][4];                    // [slot][mi][ni][frag]
    #pragma unroll
    for (int a = 0; a < 2; a++)
        #pragma unroll
        for (int m = 0; m < 2; m++)
            #pragma unroll
            for (int n = 0; n < 4; n++)
                #pragma unroll
                for (int q = 0; q < 4; q++) acc[a][m][n][q] = 0.f;

    for (int kc = 0; kc < 10; kc++) {
        // ---- A fill: 4 variants x 128 rows x 32 k = 2048 uint4, 8/thread
        #pragma unroll
        for (int i = 0; i < 8; i++) {
            int idx = tid + i * 256;
            int v = idx >> 9, rr = (idx >> 2) & 127, c8 = idx & 3;
            int e = (v >> 1) ? e1 : e0;
            const __nv_bfloat16* src = (v & 1) ? &d_Al[e][0][0] : &d_Ah[e][0][0];
            uint4 val = *(const uint4*)(src + (size_t)(r0 + rr) * 320 + kc * 32 + c8 * 8);
            *(uint4*)(As + v * (128 * K3_AS_STRIDE) + rr * K3_AS_STRIDE + c8 * 8) = val;
        }
        // ---- B fill
        if (kc < 2) {   // h2 rows (k 0..63): per-slot hi/lo = 4 variants
            #pragma unroll
            for (int i = 0; i < 4; i++) {
                int idx = tid + i * 256;
                int v = idx >> 8, n = (idx >> 2) & 63, c8 = idx & 3;
                int sl = v >> 1;
                const __nv_bfloat16* src = (v & 1) ? &d_h2tl[sl][b][0][0]
                                                   : &d_h2th[sl][b][0][0];
                uint4 val = *(const uint4*)(src + (size_t)(ct + n) * 64 + kc * 32 + c8 * 8);
                *(uint4*)(Bs + v * (64 * K3_AS_STRIDE) + n * K3_AS_STRIDE + c8 * 8) = val;
            }
        } else {        // x rows (k 64..319): shared hi/lo = 2 variants
            #pragma unroll
            for (int i = 0; i < 2; i++) {
                int idx = tid + i * 256;
                int v = idx >> 8, n = (idx >> 2) & 63, c8 = idx & 3;
                const __nv_bfloat16* src = v ? &d_xtl[b][0][0] : &d_xth[b][0][0];
                uint4 val = *(const uint4*)(src + (size_t)(ct + n) * 256 +
                                            (kc - 2) * 32 + c8 * 8);
                *(uint4*)(Bs + v * (64 * K3_AS_STRIDE) + n * K3_AS_STRIDE + c8 * 8) = val;
            }
        }
        __syncthreads();

        #pragma unroll
        for (int sl = 0; sl < 2; sl++) {
            #pragma unroll
            for (int vp = 0; vp < 3; vp++) {
                int av = sl * 2 + (vp == 2 ? 1 : 0);
                int bv = (kc < 2) ? (sl * 2 + (vp == 1 ? 1 : 0)) : (vp == 1 ? 1 : 0);
                const __nv_bfloat16* Ab = As + av * (128 * K3_AS_STRIDE);
                const __nv_bfloat16* Bb = Bs + bv * (64 * K3_AS_STRIDE);
                #pragma unroll
                for (int ks = 0; ks < 32; ks += 16) {
                    uint32_t bf[4][2];
                    #pragma unroll
                    for (int ni = 0; ni < 4; ni++) {
                        int n = wn * 32 + ni * 8 + g;
                        bf[ni][0] = *(const uint32_t*)(Bb + n * K3_AS_STRIDE + ks + tig * 2);
                        bf[ni][1] = *(const uint32_t*)(Bb + n * K3_AS_STRIDE + ks + tig * 2 + 8);
                    }
                    #pragma unroll
                    for (int mi = 0; mi < 2; mi++) {
                        int m = wm * 32 + mi * 16;
                        uint32_t a0 = *(const uint32_t*)(Ab + (m + g) * K3_AS_STRIDE + ks + tig * 2);
                        uint32_t a1 = *(const uint32_t*)(Ab + (m + g + 8) * K3_AS_STRIDE + ks + tig * 2);
                        uint32_t a2 = *(const uint32_t*)(Ab + (m + g) * K3_AS_STRIDE + ks + tig * 2 + 8);
                        uint32_t a3 = *(const uint32_t*)(Ab + (m + g + 8) * K3_AS_STRIDE + ks + tig * 2 + 8);
                        #pragma unroll
                        for (int ni = 0; ni < 4; ni++)
                            mma16816(acc[sl][mi][ni], a0, a1, a2, a3,
                                     bf[ni][0], bf[ni][1]);
                    }
                }
            }
        }
        __syncthreads();
    }

    // ---- epilogue: fuse bias + relu + gates, both slots, write once
    #pragma unroll
    for (int mi = 0; mi < 2; mi++) {
        int rowA = r0 + wm * 32 + mi * 16 + g;
        int rowB = rowA + 8;
        float b0a = b3[e0 * C_ + rowA] + bp[e0 * C_ + rowA];
        float b1a = b3[e1 * C_ + rowA] + bp[e1 * C_ + rowA];
        float b0b = b3[e0 * C_ + rowB] + bp[e0 * C_ + rowB];
        float b1b = b3[e1 * C_ + rowB] + bp[e1 * C_ + rowB];
        #pragma unroll
        for (int ni = 0; ni < 4; ni++) {
            int col = ct + wn * 32 + ni * 8 + tig * 2;
            float2 oA, oB;
            oA.x = g0 * fmaxf(acc[0][mi][ni][0] + b0a, 0.f)
                 + g1 * fmaxf(acc[1][mi][ni][0] + b1a, 0.f);
            oA.y = g0 * fmaxf(acc[0][mi][ni][1] + b0a, 0.f)
                 + g1 * fmaxf(acc[1][mi][ni][1] + b1a, 0.f);
            oB.x = g0 * fmaxf(acc[0][mi][ni][2] + b0b, 0.f)
                 + g1 * fmaxf(acc[1][mi][ni][2] + b1b, 0.f);
            oB.y = g0 * fmaxf(acc[0][mi][ni][3] + b0b, 0.f)
                 + g1 * fmaxf(acc[1][mi][ni][3] + b1b, 0.f);
            *(float2*)(out + ((size_t)b * C_ + rowA) * L_ + col) = oA;
            *(float2*)(out + ((size_t)b * C_ + rowB) * L_ + col) = oB;
        }
    }
}

// ---------------- launch ----------------------------------------------------
extern "C" void kernel_launch(void* const* d_in, const int* in_sizes, int n_in,
                              void* d_out, int out_size) {
    const float* x     = (const float*)d_in[0];
    const float* noise = (const float*)d_in[1];
    const float* wg    = (const float*)d_in[2];
    const float* wn    = (const float*)d_in[3];
    const float* W1    = (const float*)d_in[4];
    const float* b1    = (const float*)d_in[5];
    const float* W2    = (const float*)d_in[6];
    const float* b2    = (const float*)d_in[7];
    const float* W3    = (const float*)d_in[8];
    const float* b3    = (const float*)d_in[9];
    const float* Wp    = (const float*)d_in[10];
    const float* bp    = (const float*)d_in[11];
    float* out = (float*)d_out;

    long long N = (long long)B_ * C_ * L_;
    long long lidx = ((long long)out_size > N) ? N : ((long long)out_size - 1);

    cudaFuncSetAttribute(k3mma_kernel,
                         cudaFuncAttributeMaxDynamicSharedMemorySize, K3_SMEM);

    tr_w1<<<64, 256>>>(W1);
    tr_w2<<<64, 256>>>(W2);
    conv_w<<<256, 256>>>(W3, Wp);
    conv_xt<<<dim3(L_ / 32, C_ / 32, B_), dim3(32, 8)>>>(x);

    gatex_kernel<<<B_ * C_, 256>>>(x);
    gate_kernel<<<1, 64>>>(noise, wg, wn, out, lidx);

    dim3 g12(L_ / 128, B_, 2);
    k1_kernel<<<g12, 128>>>(x, b1);
    k2_kernel<<<g12, 256>>>(b2);
    conv_h2t<<<dim3(L_ / 32, 2, 2 * B_), dim3(32, 8)>>>();

    k3mma_kernel<<<dim3(L_ / 64, C_ / 128, B_), 256, K3_SMEM>>>(b3, bp, out);
}